// round 5
// baseline (speedup 1.0000x reference)
#include <cuda_runtime.h>
#include <cuda_bf16.h>
#include <cstdint>
#include <math.h>

#define B_   64
#define S_   2048
#define H_   256
#define KX   272      // 256 h + 4 feat + 1 bias + 11 pad
#define KT   34       // k's per thread (8 k-groups)
#define NTH  512
#define CL   8        // CTAs per cluster
#define ROWS 128      // gate rows per CTA (4 gates x 32 units)

// classifier config
#define TM   64
#define CTH  256
#define APAD 260
#define BPAD 258

// scratch: lstm hidden states [B][S][H] (static device alloc = allowed)
__device__ float g_lstm[(size_t)B_ * S_ * H_];

__device__ __forceinline__ float sigm(float v) { return 1.0f / (1.0f + __expf(-v)); }

__device__ __forceinline__ uint32_t smem_u32(const void* p) {
    uint32_t a;
    asm("{ .reg .u64 t; cvta.to.shared.u64 t, %1; cvt.u32.u64 %0, t; }" : "=r"(a) : "l"(p));
    return a;
}

// =====================================================================
// Recurrent LSTM: 16 clusters x 8 CTAs; weights live in registers.
// =====================================================================
__global__ void __launch_bounds__(NTH, 1) __cluster_dims__(CL, 1, 1)
lstm_kernel(const float* __restrict__ x, const float* __restrict__ conv_w,
            const float* __restrict__ conv_b, const float* __restrict__ w_ih,
            const float* __restrict__ w_hh, const float* __restrict__ b_ih,
            const float* __restrict__ b_hh)
{
    __shared__ float4 hbuf4[2 * KX];          // [buf][k] x 4 batches
    __shared__ float  red[8 * ROWS * 4];      // [kgroup][row][batch]
    __shared__ float  stage[32 * 4];          // [unit][batch]
    float* hbuf_f = (float*)hbuf4;

    const int tid   = threadIdx.x;
    const int crank = blockIdx.x & (CL - 1);
    const int ci    = blockIdx.x >> 3;

    // ---- per-thread weight registers: 2 rows x 34 k's ----
    const int r0 = (tid & 63) * 2;
    const int kg = tid >> 6;
    float w0r[KT], w1r[KT];
    {
        const int g0 = (r0 >> 5), u0 = (r0 & 31);
        const int g1 = ((r0 + 1) >> 5), u1 = ((r0 + 1) & 31);
        const int grow0 = g0 * H_ + crank * 32 + u0;
        const int grow1 = g1 * H_ + crank * 32 + u1;
        #pragma unroll
        for (int i = 0; i < KT; ++i) {
            int k = kg * KT + i;
            float a, b;
            if (k < H_)            { a = w_hh[grow0 * H_ + k];        b = w_hh[grow1 * H_ + k]; }
            else if (k < H_ + 4)   { a = w_ih[grow0 * 4 + (k - H_)];  b = w_ih[grow1 * 4 + (k - H_)]; }
            else if (k == H_ + 4)  { a = b_ih[grow0] + b_hh[grow0];   b = b_ih[grow1] + b_hh[grow1]; }
            else                   { a = 0.f;                          b = 0.f; }
            w0r[i] = a; w1r[i] = b;
        }
    }

    // ---- init shared state ----
    for (int i = tid; i < 2 * KX * 4; i += NTH) hbuf_f[i] = 0.f;
    __syncthreads();
    if (tid < 8) {  // bias row k=260 := 1.0 in both buffers (never overwritten)
        int buf = tid >> 2, b = tid & 3;
        hbuf_f[(buf * KX + 260) * 4 + b] = 1.0f;
    }
    float4 xreg = make_float4(0.f, 0.f, 0.f, 0.f);
    float4 cw = xreg, cb = xreg;
    if (tid >= 256 && tid < 260) {  // one feat thread per batch
        int b = tid - 256;
        cw = *(const float4*)conv_w;
        cb = *(const float4*)conv_b;
        const float4* xp = (const float4*)x;
        float4 x0 = xp[(size_t)(ci * 4 + b) * S_ + 0];
        hbuf_f[(0 * KX + 256) * 4 + b] = sigm(x0.x * cw.x + cb.x);
        hbuf_f[(0 * KX + 257) * 4 + b] = sigm(x0.y * cw.y + cb.y);
        hbuf_f[(0 * KX + 258) * 4 + b] = sigm(x0.z * cw.z + cb.z);
        hbuf_f[(0 * KX + 259) * 4 + b] = sigm(x0.w * cw.w + cb.w);
        xreg = xp[(size_t)(ci * 4 + b) * S_ + 1];
    }
    float creg = 0.f;  // cell state, private to gate threads (tid<128)

    asm volatile("barrier.cluster.arrive.aligned;" ::: "memory");
    asm volatile("barrier.cluster.wait.aligned;" ::: "memory");

    // ---- main sequential loop ----
    for (int t = 0; t < S_; ++t) {
        const int cur = t & 1, nxt = cur ^ 1;

        // phase A: fused matvec, batches packed as f32x2 pairs
        {
            const ulonglong2* hp = (const ulonglong2*)(hbuf4 + cur * KX + kg * KT);
            unsigned long long a00 = 0ull, a01 = 0ull, a10 = 0ull, a11 = 0ull;
            #pragma unroll
            for (int i = 0; i < KT; ++i) {
                ulonglong2 hv = hp[i];
                unsigned long long p0, p1;
                asm("mov.b64 %0, {%1, %1};" : "=l"(p0) : "r"(__float_as_int(w0r[i])));
                asm("mov.b64 %0, {%1, %1};" : "=l"(p1) : "r"(__float_as_int(w1r[i])));
                asm("fma.rn.f32x2 %0, %1, %2, %0;" : "+l"(a00) : "l"(p0), "l"(hv.x));
                asm("fma.rn.f32x2 %0, %1, %2, %0;" : "+l"(a01) : "l"(p0), "l"(hv.y));
                asm("fma.rn.f32x2 %0, %1, %2, %0;" : "+l"(a10) : "l"(p1), "l"(hv.x));
                asm("fma.rn.f32x2 %0, %1, %2, %0;" : "+l"(a11) : "l"(p1), "l"(hv.y));
            }
            ulonglong2* rp2 = (ulonglong2*)red;
            ulonglong2 v0; v0.x = a00; v0.y = a01;
            ulonglong2 v1; v1.x = a10; v1.y = a11;
            rp2[kg * ROWS + r0]     = v0;
            rp2[kg * ROWS + r0 + 1] = v1;
        }
        __syncthreads();

        // phase B: reduce + gates + cell update (tid<128); feat(t+1) (tid 256..259)
        if (tid < 128) {
            int b = tid >> 5, u = tid & 31;
            float gi = 0.f, gf = 0.f, gg = 0.f, go = 0.f;
            #pragma unroll
            for (int q = 0; q < 8; ++q) {
                gi += red[(q * ROWS +      u) * 4 + b];
                gf += red[(q * ROWS + 32 + u) * 4 + b];
                gg += red[(q * ROWS + 64 + u) * 4 + b];
                go += red[(q * ROWS + 96 + u) * 4 + b];
            }
            float iv = sigm(gi), fv = sigm(gf), ov = sigm(go);
            float gv = tanhf(gg);
            creg = fv * creg + iv * gv;
            float h = ov * tanhf(creg);
            stage[u * 4 + b] = h;
            g_lstm[((size_t)(ci * 4 + b) * S_ + t) * H_ + crank * 32 + u] = h;
        } else if (tid >= 256 && tid < 260) {
            int b = tid - 256;
            if (t + 1 < S_) {
                float* hn = hbuf_f + ((size_t)nxt * KX + 256) * 4;
                hn[0 * 4 + b] = sigm(xreg.x * cw.x + cb.x);
                hn[1 * 4 + b] = sigm(xreg.y * cw.y + cb.y);
                hn[2 * 4 + b] = sigm(xreg.z * cw.z + cb.z);
                hn[3 * 4 + b] = sigm(xreg.w * cw.w + cb.w);
            }
            int tn = (t + 2 < S_) ? (t + 2) : (S_ - 1);
            xreg = ((const float4*)x)[(size_t)(ci * 4 + b) * S_ + tn];
        }
        __syncthreads();

        // phase C: DSMEM broadcast — one float4 store per thread (256 threads)
        if (tid < 256) {
            int u = tid >> 3, p = tid & 7;
            float4 v = ((float4*)stage)[u];
            uint32_t laddr = smem_u32(&hbuf4[nxt * KX + crank * 32 + u]);
            uint32_t raddr;
            asm("mapa.shared::cluster.u32 %0, %1, %2;" : "=r"(raddr) : "r"(laddr), "r"(p));
            asm volatile("st.shared::cluster.v4.f32 [%0], {%1, %2, %3, %4};"
                         :: "r"(raddr), "f"(v.x), "f"(v.y), "f"(v.z), "f"(v.w) : "memory");
        }
        asm volatile("barrier.cluster.arrive.aligned;" ::: "memory");
        asm volatile("barrier.cluster.wait.aligned;" ::: "memory");
    }
}

// =====================================================================
// Classifier: relu(W1) + relu(W2) + W3, fused, 64-row tiles, f32x2 FMAs
// =====================================================================
__global__ void __launch_bounds__(CTH, 1)
cls_kernel(const float* __restrict__ w1, const float* __restrict__ b1,
           const float* __restrict__ w2, const float* __restrict__ b2,
           const float* __restrict__ w3, const float* __restrict__ b3,
           float* __restrict__ out)
{
    extern __shared__ float sm[];
    float* Asm = sm;                   // [64][APAD]
    float* Bsm = sm + TM * APAD;       // [64 kk][BPAD] (256 out cols + pad)
    float* w3s = Bsm + 64 * BPAD;      // [512]

    const int tid = threadIdx.x;
    const size_t n0 = (size_t)blockIdx.x * TM;

    for (int idx = tid; idx < TM * H_; idx += CTH) {
        int rr = idx >> 8, cc = idx & 255;
        Asm[rr * APAD + cc] = g_lstm[n0 * H_ + idx];
    }
    for (int idx = tid; idx < 2 * H_; idx += CTH) w3s[idx] = w3[idx];

    const int rg = tid >> 5, cgp = tid & 31;
    const int row0 = rg * 8, col0 = cgp * 8;

    for (int layer = 0; layer < 2; ++layer) {
        const float* W    = layer ? w2 : w1;
        const float* bias = layer ? b2 : b1;
        unsigned long long acc[8][4];
        #pragma unroll
        for (int i = 0; i < 8; ++i)
            #pragma unroll
            for (int j = 0; j < 4; ++j) acc[i][j] = 0ull;

        for (int kt = 0; kt < 4; ++kt) {
            __syncthreads();   // prev Bsm users done / Asm writes visible
            for (int idx = tid; idx < 64 * H_; idx += CTH) {
                int oc = idx >> 6, kk = idx & 63;
                Bsm[kk * BPAD + oc] = W[oc * H_ + kt * 64 + kk];
            }
            __syncthreads();
            const float* ap = Asm + row0 * APAD + kt * 64;
            const float* bp = Bsm + col0;
            #pragma unroll 4
            for (int kk = 0; kk < 64; ++kk) {
                const unsigned long long* bq = (const unsigned long long*)(bp + kk * BPAD);
                unsigned long long bv0 = bq[0], bv1 = bq[1], bv2 = bq[2], bv3 = bq[3];
                #pragma unroll
                for (int i = 0; i < 8; ++i) {
                    float a = ap[i * APAD + kk];
                    unsigned long long aa;
                    asm("mov.b64 %0, {%1, %1};" : "=l"(aa) : "r"(__float_as_int(a)));
                    asm("fma.rn.f32x2 %0, %1, %2, %0;" : "+l"(acc[i][0]) : "l"(aa), "l"(bv0));
                    asm("fma.rn.f32x2 %0, %1, %2, %0;" : "+l"(acc[i][1]) : "l"(aa), "l"(bv1));
                    asm("fma.rn.f32x2 %0, %1, %2, %0;" : "+l"(acc[i][2]) : "l"(aa), "l"(bv2));
                    asm("fma.rn.f32x2 %0, %1, %2, %0;" : "+l"(acc[i][3]) : "l"(aa), "l"(bv3));
                }
            }
        }
        __syncthreads();   // all FMA readers of Asm done before overwrite
        #pragma unroll
        for (int i = 0; i < 8; ++i) {
            #pragma unroll
            for (int j = 0; j < 4; ++j) {
                float px, py;
                asm("mov.b64 {%0, %1}, %2;" : "=f"(px), "=f"(py) : "l"(acc[i][j]));
                int c0 = col0 + j * 2;
                float v0 = px + bias[c0];
                float v1 = py + bias[c0 + 1];
                v0 = v0 > 0.f ? v0 : 0.f;
                v1 = v1 > 0.f ? v1 : 0.f;
                Asm[(row0 + i) * APAD + c0]     = v0;
                Asm[(row0 + i) * APAD + c0 + 1] = v1;
            }
        }
    }
    __syncthreads();

    // final projection H -> 2
    if (tid < 128) {
        int row = tid >> 1, cls = tid & 1;
        const float* ap = Asm + row * APAD;
        const float* wp = w3s + cls * H_;
        float s = b3[cls];
        #pragma unroll 8
        for (int k = 0; k < H_; ++k) s += ap[k] * wp[k];
        out[(n0 + row) * 2 + cls] = s;
    }
}

static const int CLS_SMEM = (TM * APAD + 64 * BPAD + 512) * 4;

extern "C" void kernel_launch(void* const* d_in, const int* in_sizes, int n_in,
                              void* d_out, int out_size) {
    const float* x      = (const float*)d_in[0];
    const float* conv_w = (const float*)d_in[1];
    const float* conv_b = (const float*)d_in[2];
    const float* w_ih   = (const float*)d_in[3];
    const float* w_hh   = (const float*)d_in[4];
    const float* b_ih   = (const float*)d_in[5];
    const float* b_hh   = (const float*)d_in[6];
    const float* w1     = (const float*)d_in[7];
    const float* b1     = (const float*)d_in[8];
    const float* w2     = (const float*)d_in[9];
    const float* b2     = (const float*)d_in[10];
    const float* w3     = (const float*)d_in[11];
    const float* b3     = (const float*)d_in[12];
    float* out = (float*)d_out;

    cudaFuncSetAttribute(cls_kernel, cudaFuncAttributeMaxDynamicSharedMemorySize, CLS_SMEM);

    lstm_kernel<<<128, NTH>>>(x, conv_w, conv_b, w_ih, w_hh, b_ih, b_hh);
    cls_kernel<<<(B_ * S_) / TM, CTH, CLS_SMEM>>>(w1, b1, w2, b2, w3, b3, out);
}